// round 11
// baseline (speedup 1.0000x reference)
#include <cuda_runtime.h>

// ---------------------------------------------------------------------------
// CMIAttentionMatrixForAcrobot, restructured (vectored-atomic column reductions)
// with L2 eviction-priority hints (256-bit hinted loads, as sm_103 requires):
//   T[j,i]   = sum_n data_q[n,i] * W_lin[j,n]            (splitk -> red.v4 into g_T)
//   k[j,m]   = sum_i data_k[j,i] * W_k[m,i] + b_k[m]     (row-GEMV partials slot0)
//   nq[m,j]  = sum_i W_q[m,i] * T[j,i] + b_q[m]*slin[j] + b_lin[j]  (slot1)
//   kmod     = relu6(k^2 + 2k + nq*(1+|k|))              (vsplit prologue)
//   v[j,i]   = sum_m W_q[m,i] * kmod[j,m]                (splitk -> red.v4 into g_v)
//   c[j]     = sum_m b_q[m] * kmod[j,m]                  (epilogue B, per-block)
//   out[n,j] = (sum_i data_q[n,i] * v[j,i] + c[j]) / 64  (row-GEMV slot0 + epi B)
// Cache policy: nq pins W_q with L2::evict_last so vsplit re-reads hit L2
// (64MB < 126MB L2); dead streams (W_k, dot's data_q) use L2::evict_first.
// 5 launches total.
// ---------------------------------------------------------------------------

typedef unsigned long long u64;

#define N_DIM 4096
#define JD 6
#define NTHR 256

// T splitk: 64 rows x 1024 cols per block
#define RPS_T 64
#define NSPLIT_T 64
#define SPLITK_T_BLOCKS (4 * NSPLIT_T)    // 256
// v splitk: 32 rows x 1024 cols per block
#define RPS_V 32
#define NSPLIT_V 128

// row-GEMV: 16 rows (8 warps x 2 rows) x 512 cols per block
#define KSPLIT 8
#define CPK (N_DIM / KSPLIT)              // 512
#define RGROWS 16
#define RGX (N_DIM / RGROWS)              // 256
#define RG_BLOCKS (RGX * KSPLIT)          // 2048

#define EPIB_BLOCKS 32

// load policies
#define POL_N  0   // normal
#define POL_EF 1   // L2::evict_first (streaming, dead after use)
#define POL_EL 2   // L2::evict_last  (pin for the next pass)

// scratch (static device globals; zero-initialized at module load)
__device__ float g_T[JD * N_DIM];
__device__ float g_v[JD * N_DIM];
__device__ float g_kmod[JD * N_DIM];
__device__ float g_rgpart[2 * KSPLIT * N_DIM * JD];   // slot0: k then dot; slot1: nq
__device__ float g_slin[JD];

// ---- packed fp32x2 helpers ------------------------------------------------
__device__ __forceinline__ u64 pk2(float a, float b) {
    u64 r;
    asm("mov.b64 %0, {%1, %2};" : "=l"(r) : "r"(__float_as_uint(a)), "r"(__float_as_uint(b)));
    return r;
}
__device__ __forceinline__ float2 upk(u64 v) {
    unsigned lo, hi;
    asm("mov.b64 {%0, %1}, %2;" : "=r"(lo), "=r"(hi) : "l"(v));
    return make_float2(__uint_as_float(lo), __uint_as_float(hi));
}
__device__ __forceinline__ void fma2(u64& d, u64 a, u64 b) {
    asm("fma.rn.f32x2 %0, %1, %2, %0;" : "+l"(d) : "l"(a), "l"(b));
}
__device__ __forceinline__ void add2(u64& d, u64 a) {
    asm("add.rn.f32x2 %0, %0, %1;" : "+l"(d) : "l"(a));
}
// vectored global float reduction (sm_90+), 4 floats per op
__device__ __forceinline__ void red4(float* gp, float a, float b, float c, float d) {
    asm volatile(
        "{\n\t.reg .u64 p;\n\t"
        "cvta.to.global.u64 p, %0;\n\t"
        "red.global.add.v4.f32 [p], {%1, %2, %3, %4};\n\t}"
        :: "l"(gp), "f"(a), "f"(b), "f"(c), "f"(d) : "memory");
}
// 32B global load (v4.u64 = 8 floats) with an L2 eviction-priority policy.
// sm_103 ptxas only accepts L2::evict_* on 256-bit loads.
struct u64x4 { u64 a, b, c, d; };
template<int POL>
__device__ __forceinline__ u64x4 ldg4(const void* __restrict__ p) {
    u64x4 r;
    if (POL == POL_EF) {
        asm("ld.global.nc.L2::evict_first.v4.u64 {%0, %1, %2, %3}, [%4];"
            : "=l"(r.a), "=l"(r.b), "=l"(r.c), "=l"(r.d) : "l"(p));
    } else if (POL == POL_EL) {
        asm("ld.global.nc.L2::evict_last.v4.u64 {%0, %1, %2, %3}, [%4];"
            : "=l"(r.a), "=l"(r.b), "=l"(r.c), "=l"(r.d) : "l"(p));
    } else {
        asm("ld.global.nc.v4.u64 {%0, %1, %2, %3}, [%4];"
            : "=l"(r.a), "=l"(r.b), "=l"(r.c), "=l"(r.d) : "l"(p));
    }
    return r;
}

// --------------------------------------------------------------------------
// bodies (256-thread blocks)
// --------------------------------------------------------------------------
__device__ __forceinline__ void slin_body(const float* __restrict__ Wlin) {
    const int wid = threadIdx.x >> 5;
    const int lane = threadIdx.x & 31;
    if (wid < JD) {
        const float4* p = (const float4*)(Wlin + wid * N_DIM);
        float s = 0.0f;
        for (int q = lane; q < N_DIM / 4; q += 32) {
            float4 v = p[q];
            s += v.x + v.y + v.z + v.w;
        }
        #pragma unroll
        for (int o = 16; o; o >>= 1) s += __shfl_xor_sync(0xffffffffu, s, o);
        if (lane == 0) g_slin[wid] = s;
    }
}

// split-K accumulation core: RPS_ rows x 1024 cols, ws[j][rr] in smem already.
// Plain 16B loads (no hint needed; residency decided by the nq pass's pins).
template<int RPS_>
__device__ __forceinline__ void splitk_accum(const float* __restrict__ big,
                                             float* __restrict__ out,
                                             int cslab, int r0,
                                             const float (*ws)[RPS_]) {
    const int tid = threadIdx.x;
    const int c0 = cslab * 1024 + tid * 4;

    u64 acc[JD][2];
    #pragma unroll
    for (int j = 0; j < JD; j++) { acc[j][0] = 0ull; acc[j][1] = 0ull; }

    const ulonglong2* bp = (const ulonglong2*)big + (((size_t)r0 * N_DIM + c0) >> 2);
    #pragma unroll 4
    for (int rr = 0; rr < RPS_; rr++) {
        ulonglong2 d = bp[(size_t)rr * (N_DIM / 4)];
        #pragma unroll
        for (int j = 0; j < JD; j++) {
            u64 wp = pk2(ws[j][rr], ws[j][rr]);
            fma2(acc[j][0], d.x, wp);
            fma2(acc[j][1], d.y, wp);
        }
    }

    #pragma unroll
    for (int j = 0; j < JD; j++) {
        float2 a = upk(acc[j][0]), b = upk(acc[j][1]);
        red4(out + j * N_DIM + c0, a.x, a.y, b.x, b.y);
    }
}

// split-K with ws loaded from a global factor matrix w[j*N + r].
template<int RPS_>
__device__ __forceinline__ void splitk_body(const float* __restrict__ big,
                                            const float* __restrict__ w,
                                            float* __restrict__ out,
                                            int cslab, int split,
                                            float (*ws)[RPS_]) {
    const int tid = threadIdx.x;
    const int r0 = split * RPS_;
    for (int idx = tid; idx < JD * RPS_; idx += NTHR) {
        int j = idx / RPS_, rr = idx % RPS_;
        ws[j][rr] = w[j * N_DIM + r0 + rr];
    }
    __syncthreads();
    splitk_accum<RPS_>(big, out, cslab, r0, (const float (*)[RPS_])ws);
}

// row-GEMV: 16 rows (8 warps x 2 rows) x CPK cols per block, KSPLIT col splits.
// Streams use 32B hinted loads (8 floats per lane per row per iteration).
template<int POL>
__device__ __forceinline__ void rowgemv_body(const float* __restrict__ big,
                                             const float* __restrict__ S,
                                             float* __restrict__ partbase,
                                             int rowblk, int ks,
                                             ulonglong2 (*ss)[CPK / 4]) {
    const int tid = threadIdx.x;
    const int wid = tid >> 5;
    const int lane = tid & 31;
    const int cbase = ks * CPK;
    const int r0 = rowblk * RGROWS + wid * 2;

    for (int idx = tid; idx < JD * (CPK / 4); idx += NTHR) {
        int j = idx >> 7, q = idx & 127;
        ss[j][q] = ((const ulonglong2*)(S + j * N_DIM + cbase))[q];
    }
    __syncthreads();

    u64 a0[JD], a1[JD];
    #pragma unroll
    for (int j = 0; j < JD; j++) { a0[j] = 0ull; a1[j] = 0ull; }

    const char* r0base = (const char*)(big + (size_t)(r0 + 0) * N_DIM + cbase);
    const char* r1base = (const char*)(big + (size_t)(r0 + 1) * N_DIM + cbase);

    #pragma unroll
    for (int it = 0; it < CPK / 256; it++) {     // 2 iterations of 32B chunks
        const int q = it * 32 + lane;            // 32B-chunk index (0..63)
        u64x4 m0 = ldg4<POL>(r0base + q * 32);
        u64x4 m1 = ldg4<POL>(r1base + q * 32);
        #pragma unroll
        for (int j = 0; j < JD; j++) {
            ulonglong2 s0 = ss[j][2 * q];
            ulonglong2 s1 = ss[j][2 * q + 1];
            fma2(a0[j], m0.a, s0.x); fma2(a0[j], m0.b, s0.y);
            fma2(a0[j], m0.c, s1.x); fma2(a0[j], m0.d, s1.y);
            fma2(a1[j], m1.a, s0.x); fma2(a1[j], m1.b, s0.y);
            fma2(a1[j], m1.c, s1.x); fma2(a1[j], m1.d, s1.y);
        }
    }

    #pragma unroll
    for (int j = 0; j < JD; j++) {
        #pragma unroll
        for (int o = 16; o; o >>= 1) {
            add2(a0[j], __shfl_xor_sync(0xffffffffu, a0[j], o));
            add2(a1[j], __shfl_xor_sync(0xffffffffu, a1[j], o));
        }
    }

    if (lane == 0) {
        float* p = partbase + (size_t)ks * (N_DIM * JD);
        #pragma unroll
        for (int j = 0; j < JD; j++) {
            float2 f0 = upk(a0[j]), f1 = upk(a1[j]);
            p[(size_t)r0 * JD + j] = f0.x + f0.y;
            p[(size_t)(r0 + 1) * JD + j] = f1.x + f1.y;
        }
    }
}

// --------------------------------------------------------------------------
// Phase 1: T-splitk (red.v4 into g_T) + k-rowgemv (slot0, evict_first) + slin.
// --------------------------------------------------------------------------
__global__ void __launch_bounds__(NTHR) phase1_kernel(
        const float* __restrict__ data_q, const float* __restrict__ W_lin,
        const float* __restrict__ W_k,    const float* __restrict__ data_k) {
    __shared__ ulonglong2 ss[JD][CPK / 4];   // 12KB (splitk aliases as ws)
    const int bid = blockIdx.x;
    if (bid < SPLITK_T_BLOCKS) {
        splitk_body<RPS_T>(data_q, W_lin, g_T, bid & 3, bid >> 2, (float (*)[RPS_T])ss);
    } else if (bid < SPLITK_T_BLOCKS + RG_BLOCKS) {
        const int rb = bid - SPLITK_T_BLOCKS;
        rowgemv_body<POL_EF>(W_k, data_k, g_rgpart, rb >> 3, rb & 7, ss);
    } else {
        slin_body(W_lin);
    }
}

// nq pass: W_q x g_T -> slot1 partials. W_q loads pinned (evict_last) so the
// immediately following vsplit pass re-reads them from L2.
__global__ void __launch_bounds__(NTHR) nq_kernel(const float* __restrict__ W_q) {
    __shared__ ulonglong2 ss[JD][CPK / 4];
    rowgemv_body<POL_EL>(W_q, g_T, g_rgpart + (size_t)KSPLIT * N_DIM * JD,
                         blockIdx.x, blockIdx.y, ss);
}

// v pass: prologue computes kmod for this block's 32 rows from k/nq partials,
// then splitk over W_q (L2-resident from nq's pins) into g_v.
// cslab 0 persists g_kmod for epilogueB's c-sum.
__global__ void __launch_bounds__(NTHR) vsplit_kernel(
        const float* __restrict__ W_q, const float* __restrict__ b_k,
        const float* __restrict__ b_q, const float* __restrict__ b_lin) {
    __shared__ float ws[JD][RPS_V];
    const int tid = threadIdx.x;
    const int cslab = blockIdx.x;
    const int r0 = blockIdx.y * RPS_V;

    if (tid < JD * RPS_V) {                    // 192 threads
        const int rr = tid & 31;
        const int j = tid >> 5;
        const int m = r0 + rr;
        float kv = 0.f, nqv = 0.f;
        #pragma unroll
        for (int ks = 0; ks < KSPLIT; ks++) {
            kv  += g_rgpart[((size_t)ks * N_DIM + m) * JD + j];
            nqv += g_rgpart[((size_t)(KSPLIT + ks) * N_DIM + m) * JD + j];
        }
        kv += b_k[m];
        nqv += b_q[m] * g_slin[j] + b_lin[j];
        float x = fmaf(kv, kv, 2.0f * kv) + nqv * (1.0f + fabsf(kv));
        float km = fminf(fmaxf(x, 0.0f), 6.0f);
        ws[j][rr] = km;
        if (cslab == 0) g_kmod[j * N_DIM + m] = km;
    }
    __syncthreads();

    splitk_accum<RPS_V>(W_q, g_v, cslab, r0, (const float (*)[RPS_V])ws);
}

// dot pass: data_q x g_v -> slot0 partials (k partials consumed by vsplit).
// data_q is dead after this -> evict_first.
__global__ void __launch_bounds__(NTHR) dot_kernel(const float* __restrict__ data_q) {
    __shared__ ulonglong2 ss[JD][CPK / 4];
    rowgemv_body<POL_EF>(data_q, g_v, g_rgpart, blockIdx.x, blockIdx.y, ss);
}

// --------------------------------------------------------------------------
// Epilogue B: per-block compute c[j] = sum_m b_q[m]*kmod[j,m] (redundant x32),
// then out[m,j] = (sum_ks dotpart[ks][m][j] + c[j]) / 64.
// Tail: re-zero g_T and g_v for the next call (graph replays).
// --------------------------------------------------------------------------
__global__ void __launch_bounds__(128) epilogueB_kernel(
        const float* __restrict__ b_q, float* __restrict__ out) {
    __shared__ float red[JD][128];
    __shared__ float cs[JD];
    const int tid = threadIdx.x;

    float cl[JD];
    #pragma unroll
    for (int j = 0; j < JD; j++) cl[j] = 0.f;
    #pragma unroll 4
    for (int i = 0; i < 32; i++) {
        const int m = i * 128 + tid;
        const float b = b_q[m];
        #pragma unroll
        for (int j = 0; j < JD; j++) cl[j] = fmaf(b, g_kmod[j * N_DIM + m], cl[j]);
    }
    #pragma unroll
    for (int j = 0; j < JD; j++) red[j][tid] = cl[j];
    __syncthreads();
    for (int s = 64; s > 0; s >>= 1) {
        if (tid < s) {
            #pragma unroll
            for (int j = 0; j < JD; j++) red[j][tid] += red[j][tid + s];
        }
        __syncthreads();
    }
    if (tid < JD) cs[tid] = red[tid][0];
    __syncthreads();

    const int m = blockIdx.x * 128 + tid;
    float acc[JD];
    #pragma unroll
    for (int j = 0; j < JD; j++) acc[j] = cs[j];
    #pragma unroll
    for (int ks = 0; ks < KSPLIT; ks++) {
        const float* p = g_rgpart + ((size_t)ks * N_DIM + m) * JD;
        #pragma unroll
        for (int j = 0; j < JD; j++) acc[j] += p[j];
    }
    #pragma unroll
    for (int j = 0; j < JD; j++)
        out[m * JD + j] = acc[j] * 0.015625f;

    // tail-zero accumulators for the next invocation
    const int gt = blockIdx.x * 128 + tid;               // 4096 threads
    float4* t4 = (float4*)g_T;
    float4* v4 = (float4*)g_v;
    const float4 z = make_float4(0.f, 0.f, 0.f, 0.f);
    #pragma unroll
    for (int idx = gt; idx < JD * N_DIM / 4; idx += EPIB_BLOCKS * 128) {
        t4[idx] = z;
        v4[idx] = z;
    }
}

// --------------------------------------------------------------------------
extern "C" void kernel_launch(void* const* d_in, const int* in_sizes, int n_in,
                              void* d_out, int out_size) {
    const float* data_q = (const float*)d_in[0];   // [4096,4096]
    const float* data_k = (const float*)d_in[1];   // [6,4096]
    const float* W_q    = (const float*)d_in[2];   // [4096,4096]
    const float* b_q    = (const float*)d_in[3];   // [4096]
    const float* W_lin  = (const float*)d_in[4];   // [6,4096]
    const float* b_lin  = (const float*)d_in[5];   // [6]
    const float* W_k    = (const float*)d_in[6];   // [4096,4096]
    const float* b_k    = (const float*)d_in[7];   // [4096]
    float* out = (float*)d_out;                    // [4096,6]

    phase1_kernel<<<SPLITK_T_BLOCKS + RG_BLOCKS + 1, NTHR>>>(data_q, W_lin, W_k, data_k);
    nq_kernel<<<dim3(RGX, KSPLIT), NTHR>>>(W_q);                       // nq (pin W_q in L2)
    vsplit_kernel<<<dim3(4, NSPLIT_V), NTHR>>>(W_q, b_k, b_q, b_lin);  // kmod + v (L2 hits)
    dot_kernel<<<dim3(RGX, KSPLIT), NTHR>>>(data_q);                   // dot partials
    epilogueB_kernel<<<EPIB_BLOCKS, 128>>>(b_q, out);                  // c + out + re-zero
}

// round 12
// speedup vs baseline: 1.1510x; 1.1510x over previous
#include <cuda_runtime.h>

// ---------------------------------------------------------------------------
// CMIAttentionMatrixForAcrobot, restructured, cp.async-pipelined streams:
//   T[j,i]   = sum_n data_q[n,i] * W_lin[j,n]            (splitk -> red.v4 into g_T)
//   k[j,m]   = sum_i data_k[j,i] * W_k[m,i] + b_k[m]     (row-GEMV partials slot0)
//   nq[m,j]  = sum_i W_q[m,i] * T[j,i] + b_q[m]*slin[j] + b_lin[j]  (slot1)
//   kmod     = relu6(k^2 + 2k + nq*(1+|k|))              (vsplit prologue)
//   v[j,i]   = sum_m W_q[m,i] * kmod[j,m]                (splitk -> red.v4 into g_v)
//   c[j]     = sum_m b_q[m] * kmod[j,m]                  (epilogue B, per-block)
//   out[n,j] = (sum_i data_q[n,i] * v[j,i] + c[j]) / 64  (row-GEMV slot0 + epi B)
// Streaming reads go through cp.async.cg (LDGSTS): in-flight depth is bounded
// by smem, not the register scoreboard, so DRAM latency is covered.
// splitk: 4-stage per-thread ring, barrier-free (each thread consumes only the
// bytes it copied). rowgemv: full-batch prefetch of the warp's 4KB stream.
// 5 launches total. g_T/g_v zero-invariant maintained by epilogueB's tail.
// ---------------------------------------------------------------------------

typedef unsigned long long u64;

#define N_DIM 4096
#define JD 6
#define NTHR 256

// T splitk: 64 rows x 1024 cols per block
#define RPS_T 64
#define NSPLIT_T 64
#define SPLITK_T_BLOCKS (4 * NSPLIT_T)    // 256
// v splitk: 32 rows x 1024 cols per block
#define RPS_V 32
#define NSPLIT_V 128

// row-GEMV: 16 rows (8 warps x 2 rows) x 512 cols per block
#define KSPLIT 8
#define CPK (N_DIM / KSPLIT)              // 512
#define RGROWS 16
#define RGX (N_DIM / RGROWS)              // 256
#define RG_BLOCKS (RGX * KSPLIT)          // 2048

#define EPIB_BLOCKS 32

// rowgemv smem layout: S-tile 12KB + stream buf 32KB
#define RG_SS_BYTES (JD * (CPK / 4) * 16)          // 12288
#define RG_SMEM (RG_SS_BYTES + RGROWS * CPK * 4)   // 45056
// splitk smem layout: ws (<=1.5KB) at 0, stream buf 16KB at 2048
#define SK_BUF_OFF 2048
#define SK_SMEM (SK_BUF_OFF + 4 * 1024 * 4)        // 18432

// scratch (static device globals; zero-initialized at module load)
__device__ float g_T[JD * N_DIM];
__device__ float g_v[JD * N_DIM];
__device__ float g_kmod[JD * N_DIM];
__device__ float g_rgpart[2 * KSPLIT * N_DIM * JD];   // slot0: k then dot; slot1: nq
__device__ float g_slin[JD];

// ---- packed fp32x2 helpers ------------------------------------------------
__device__ __forceinline__ u64 pk2(float a, float b) {
    u64 r;
    asm("mov.b64 %0, {%1, %2};" : "=l"(r) : "r"(__float_as_uint(a)), "r"(__float_as_uint(b)));
    return r;
}
__device__ __forceinline__ float2 upk(u64 v) {
    unsigned lo, hi;
    asm("mov.b64 {%0, %1}, %2;" : "=r"(lo), "=r"(hi) : "l"(v));
    return make_float2(__uint_as_float(lo), __uint_as_float(hi));
}
__device__ __forceinline__ void fma2(u64& d, u64 a, u64 b) {
    asm("fma.rn.f32x2 %0, %1, %2, %0;" : "+l"(d) : "l"(a), "l"(b));
}
__device__ __forceinline__ void add2(u64& d, u64 a) {
    asm("add.rn.f32x2 %0, %0, %1;" : "+l"(d) : "l"(a));
}
// vectored global float reduction (sm_90+), 4 floats per op
__device__ __forceinline__ void red4(float* gp, float a, float b, float c, float d) {
    asm volatile(
        "{\n\t.reg .u64 p;\n\t"
        "cvta.to.global.u64 p, %0;\n\t"
        "red.global.add.v4.f32 [p], {%1, %2, %3, %4};\n\t}"
        :: "l"(gp), "f"(a), "f"(b), "f"(c), "f"(d) : "memory");
}
// ---- cp.async helpers -------------------------------------------------------
__device__ __forceinline__ unsigned sptr(const void* p) {
    return (unsigned)__cvta_generic_to_shared(p);
}
__device__ __forceinline__ void cp16(unsigned smem_dst, const void* gmem_src) {
    asm volatile("cp.async.cg.shared.global [%0], [%1], 16;"
                 :: "r"(smem_dst), "l"(gmem_src));
}
__device__ __forceinline__ void cp_commit() {
    asm volatile("cp.async.commit_group;");
}
template<int N>
__device__ __forceinline__ void cp_wait() {
    asm volatile("cp.async.wait_group %0;" :: "n"(N));
}

// --------------------------------------------------------------------------
// bodies (256-thread blocks)
// --------------------------------------------------------------------------
__device__ __forceinline__ void slin_body(const float* __restrict__ Wlin) {
    const int wid = threadIdx.x >> 5;
    const int lane = threadIdx.x & 31;
    if (wid < JD) {
        const float4* p = (const float4*)(Wlin + wid * N_DIM);
        float s = 0.0f;
        for (int q = lane; q < N_DIM / 4; q += 32) {
            float4 v = p[q];
            s += v.x + v.y + v.z + v.w;
        }
        #pragma unroll
        for (int o = 16; o; o >>= 1) s += __shfl_xor_sync(0xffffffffu, s, o);
        if (lane == 0) g_slin[wid] = s;
    }
}

// split-K accumulation core: RPS_ rows x 1024 cols. Streaming via a 4-stage
// per-thread cp.async ring (thread tid owns cols c0..c0+3 in every stage, and
// consumes exactly the bytes it copied -> no __syncthreads in the loop).
template<int RPS_>
__device__ __forceinline__ void splitk_accum(const float* __restrict__ big,
                                             float* __restrict__ out,
                                             int cslab, int r0,
                                             const float (*ws)[RPS_],
                                             float* __restrict__ buf) {  // [4][1024]
    const int tid = threadIdx.x;
    const int c0 = cslab * 1024 + tid * 4;
    const float* gp = big + (size_t)r0 * N_DIM + c0;
    const unsigned sb = sptr(buf) + tid * 16;

    // prologue: stages 0..2 in flight
    #pragma unroll
    for (int s = 0; s < 3; s++) {
        cp16(sb + s * 4096, gp + (size_t)s * N_DIM);
        cp_commit();
    }

    u64 acc[JD][2];
    #pragma unroll
    for (int j = 0; j < JD; j++) { acc[j][0] = 0ull; acc[j][1] = 0ull; }

    #pragma unroll 4
    for (int rr = 0; rr < RPS_; rr++) {
        const int nxt = rr + 3;
        if (nxt < RPS_) cp16(sb + (nxt & 3) * 4096, gp + (size_t)nxt * N_DIM);
        cp_commit();
        cp_wait<3>();                       // stage rr complete
        ulonglong2 d = *(const ulonglong2*)(buf + (rr & 3) * 1024 + tid * 4);
        #pragma unroll
        for (int j = 0; j < JD; j++) {
            u64 wp = pk2(ws[j][rr], ws[j][rr]);
            fma2(acc[j][0], d.x, wp);
            fma2(acc[j][1], d.y, wp);
        }
    }

    #pragma unroll
    for (int j = 0; j < JD; j++) {
        float2 a = upk(acc[j][0]), b = upk(acc[j][1]);
        red4(out + j * N_DIM + c0, a.x, a.y, b.x, b.y);
    }
}

// split-K with ws loaded from a global factor matrix w[j*N + r].
template<int RPS_>
__device__ __forceinline__ void splitk_body(const float* __restrict__ big,
                                            const float* __restrict__ w,
                                            float* __restrict__ out,
                                            int cslab, int split,
                                            char* smem) {
    float (*ws)[RPS_] = (float (*)[RPS_])smem;
    float* buf = (float*)(smem + SK_BUF_OFF);
    const int tid = threadIdx.x;
    const int r0 = split * RPS_;
    for (int idx = tid; idx < JD * RPS_; idx += NTHR) {
        int j = idx / RPS_, rr = idx % RPS_;
        ws[j][rr] = w[j * N_DIM + r0 + rr];
    }
    __syncthreads();
    splitk_accum<RPS_>(big, out, cslab, r0, (const float (*)[RPS_])ws, buf);
}

// row-GEMV: 16 rows (8 warps x 2 rows) x CPK cols per block, KSPLIT col splits.
// S-tile AND the warp's entire 4KB stream prefetched via cp.async in one batch
// (8 stream copies + 3 S copies per thread in flight), then consumed from smem.
__device__ __forceinline__ void rowgemv_body(const float* __restrict__ big,
                                             const float* __restrict__ S,
                                             float* __restrict__ partbase,
                                             int rowblk, int ks,
                                             char* smem) {
    ulonglong2 (*ss)[CPK / 4] = (ulonglong2 (*)[CPK / 4])smem;
    float* buf = (float*)(smem + RG_SS_BYTES);     // [RGROWS][CPK]
    const int tid = threadIdx.x;
    const int wid = tid >> 5;
    const int lane = tid & 31;
    const int cbase = ks * CPK;
    const int r0 = rowblk * RGROWS + wid * 2;

    // S tile: JD*CPK floats = 768 16B chunks, 3 per thread
    #pragma unroll
    for (int t = 0; t < 3; t++) {
        const int idx = tid + t * NTHR;
        const int j = idx >> 7, q = idx & 127;
        cp16(sptr(&ss[j][q]), (const char*)(S + j * N_DIM + cbase) + q * 16);
    }
    // stream: warp's 2 rows x 512 floats; lane copies the chunks it consumes
    const float* g0 = big + (size_t)r0 * N_DIM + cbase;
    const float* g1 = g0 + N_DIM;
    float* b0 = buf + (wid * 2) * CPK;
    float* b1 = b0 + CPK;
    const unsigned s0 = sptr(b0), s1 = sptr(b1);
    #pragma unroll
    for (int it = 0; it < 4; it++) {
        const int q = it * 32 + lane;
        cp16(s0 + q * 16, g0 + q * 4);
        cp16(s1 + q * 16, g1 + q * 4);
    }
    cp_commit();
    cp_wait<0>();
    __syncthreads();

    u64 a0[JD], a1[JD];
    #pragma unroll
    for (int j = 0; j < JD; j++) { a0[j] = 0ull; a1[j] = 0ull; }

    #pragma unroll
    for (int it = 0; it < 4; it++) {
        const int q = it * 32 + lane;
        ulonglong2 m0 = *(const ulonglong2*)(b0 + q * 4);
        ulonglong2 m1 = *(const ulonglong2*)(b1 + q * 4);
        #pragma unroll
        for (int j = 0; j < JD; j++) {
            ulonglong2 sv = ss[j][q];
            fma2(a0[j], m0.x, sv.x); fma2(a0[j], m0.y, sv.y);
            fma2(a1[j], m1.x, sv.x); fma2(a1[j], m1.y, sv.y);
        }
    }

    #pragma unroll
    for (int j = 0; j < JD; j++) {
        #pragma unroll
        for (int o = 16; o; o >>= 1) {
            add2(a0[j], __shfl_xor_sync(0xffffffffu, a0[j], o));
            add2(a1[j], __shfl_xor_sync(0xffffffffu, a1[j], o));
        }
    }

    if (lane == 0) {
        float* p = partbase + (size_t)ks * (N_DIM * JD);
        #pragma unroll
        for (int j = 0; j < JD; j++) {
            float2 f0 = upk(a0[j]), f1 = upk(a1[j]);
            p[(size_t)r0 * JD + j] = f0.x + f0.y;
            p[(size_t)(r0 + 1) * JD + j] = f1.x + f1.y;
        }
    }
}

// --------------------------------------------------------------------------
// Phase 1: T-splitk (red.v4 into g_T) + k-rowgemv (slot0) + slin.
// --------------------------------------------------------------------------
__global__ void __launch_bounds__(NTHR) phase1_kernel(
        const float* __restrict__ data_q, const float* __restrict__ W_lin,
        const float* __restrict__ W_k,    const float* __restrict__ data_k) {
    __shared__ char smem[RG_SMEM];   // 44KB (splitk path uses the front 18KB)
    const int bid = blockIdx.x;
    if (bid < SPLITK_T_BLOCKS) {
        splitk_body<RPS_T>(data_q, W_lin, g_T, bid & 3, bid >> 2, smem);
    } else if (bid < SPLITK_T_BLOCKS + RG_BLOCKS) {
        const int rb = bid - SPLITK_T_BLOCKS;
        rowgemv_body(W_k, data_k, g_rgpart, rb >> 3, rb & 7, smem);
    } else {
        slin_body(W_lin);
    }
}

// nq pass: W_q x g_T -> slot1 partials
__global__ void __launch_bounds__(NTHR) nq_kernel(const float* __restrict__ W_q) {
    __shared__ char smem[RG_SMEM];
    rowgemv_body(W_q, g_T, g_rgpart + (size_t)KSPLIT * N_DIM * JD,
                 blockIdx.x, blockIdx.y, smem);
}

// v pass: prologue computes kmod for this block's 32 rows from k/nq partials,
// then pipelined splitk over W_q into g_v. cslab 0 persists g_kmod.
__global__ void __launch_bounds__(NTHR) vsplit_kernel(
        const float* __restrict__ W_q, const float* __restrict__ b_k,
        const float* __restrict__ b_q, const float* __restrict__ b_lin) {
    __shared__ char smem[SK_SMEM];
    float (*ws)[RPS_V] = (float (*)[RPS_V])smem;
    float* buf = (float*)(smem + SK_BUF_OFF);
    const int tid = threadIdx.x;
    const int cslab = blockIdx.x;
    const int r0 = blockIdx.y * RPS_V;

    if (tid < JD * RPS_V) {                    // 192 threads
        const int rr = tid & 31;
        const int j = tid >> 5;
        const int m = r0 + rr;
        float kv = 0.f, nqv = 0.f;
        #pragma unroll
        for (int ks = 0; ks < KSPLIT; ks++) {
            kv  += g_rgpart[((size_t)ks * N_DIM + m) * JD + j];
            nqv += g_rgpart[((size_t)(KSPLIT + ks) * N_DIM + m) * JD + j];
        }
        kv += b_k[m];
        nqv += b_q[m] * g_slin[j] + b_lin[j];
        float x = fmaf(kv, kv, 2.0f * kv) + nqv * (1.0f + fabsf(kv));
        float km = fminf(fmaxf(x, 0.0f), 6.0f);
        ws[j][rr] = km;
        if (cslab == 0) g_kmod[j * N_DIM + m] = km;
    }
    __syncthreads();

    splitk_accum<RPS_V>(W_q, g_v, cslab, r0, (const float (*)[RPS_V])ws, buf);
}

// dot pass: data_q x g_v -> slot0 partials (k partials consumed by vsplit)
__global__ void __launch_bounds__(NTHR) dot_kernel(const float* __restrict__ data_q) {
    __shared__ char smem[RG_SMEM];
    rowgemv_body(data_q, g_v, g_rgpart, blockIdx.x, blockIdx.y, smem);
}

// --------------------------------------------------------------------------
// Epilogue B: per-block compute c[j] = sum_m b_q[m]*kmod[j,m] (redundant x32),
// then out[m,j] = (sum_ks dotpart[ks][m][j] + c[j]) / 64.
// Tail: re-zero g_T and g_v for the next call (graph replays).
// --------------------------------------------------------------------------
__global__ void __launch_bounds__(128) epilogueB_kernel(
        const float* __restrict__ b_q, float* __restrict__ out) {
    __shared__ float red[JD][128];
    __shared__ float cs[JD];
    const int tid = threadIdx.x;

    float cl[JD];
    #pragma unroll
    for (int j = 0; j < JD; j++) cl[j] = 0.f;
    #pragma unroll 4
    for (int i = 0; i < 32; i++) {
        const int m = i * 128 + tid;
        const float b = b_q[m];
        #pragma unroll
        for (int j = 0; j < JD; j++) cl[j] = fmaf(b, g_kmod[j * N_DIM + m], cl[j]);
    }
    #pragma unroll
    for (int j = 0; j < JD; j++) red[j][tid] = cl[j];
    __syncthreads();
    for (int s = 64; s > 0; s >>= 1) {
        if (tid < s) {
            #pragma unroll
            for (int j = 0; j < JD; j++) red[j][tid] += red[j][tid + s];
        }
        __syncthreads();
    }
    if (tid < JD) cs[tid] = red[tid][0];
    __syncthreads();

    const int m = blockIdx.x * 128 + tid;
    float acc[JD];
    #pragma unroll
    for (int j = 0; j < JD; j++) acc[j] = cs[j];
    #pragma unroll
    for (int ks = 0; ks < KSPLIT; ks++) {
        const float* p = g_rgpart + ((size_t)ks * N_DIM + m) * JD;
        #pragma unroll
        for (int j = 0; j < JD; j++) acc[j] += p[j];
    }
    #pragma unroll
    for (int j = 0; j < JD; j++)
        out[m * JD + j] = acc[j] * 0.015625f;

    // tail-zero accumulators for the next invocation
    const int gt = blockIdx.x * 128 + tid;               // 4096 threads
    float4* t4 = (float4*)g_T;
    float4* v4 = (float4*)g_v;
    const float4 z = make_float4(0.f, 0.f, 0.f, 0.f);
    #pragma unroll
    for (int idx = gt; idx < JD * N_DIM / 4; idx += EPIB_BLOCKS * 128) {
        t4[idx] = z;
        v4[idx] = z;
    }
}

// --------------------------------------------------------------------------
extern "C" void kernel_launch(void* const* d_in, const int* in_sizes, int n_in,
                              void* d_out, int out_size) {
    const float* data_q = (const float*)d_in[0];   // [4096,4096]
    const float* data_k = (const float*)d_in[1];   // [6,4096]
    const float* W_q    = (const float*)d_in[2];   // [4096,4096]
    const float* b_q    = (const float*)d_in[3];   // [4096]
    const float* W_lin  = (const float*)d_in[4];   // [6,4096]
    const float* b_lin  = (const float*)d_in[5];   // [6]
    const float* W_k    = (const float*)d_in[6];   // [4096,4096]
    const float* b_k    = (const float*)d_in[7];   // [4096]
    float* out = (float*)d_out;                    // [4096,6]

    phase1_kernel<<<SPLITK_T_BLOCKS + RG_BLOCKS + 1, NTHR>>>(data_q, W_lin, W_k, data_k);
    nq_kernel<<<dim3(RGX, KSPLIT), NTHR>>>(W_q);                       // nq partials
    vsplit_kernel<<<dim3(4, NSPLIT_V), NTHR>>>(W_q, b_k, b_q, b_lin);  // kmod + v
    dot_kernel<<<dim3(RGX, KSPLIT), NTHR>>>(data_q);                   // dot partials
    epilogueB_kernel<<<EPIB_BLOCKS, 128>>>(b_q, out);                  // c + out + re-zero
}